// round 1
// baseline (speedup 1.0000x reference)
#include <cuda_runtime.h>
#include <cuda_bf16.h>
#include <math.h>

// Problem constants
#define BB   16384
#define DD   1024
#define PP   1024
#define OUTC 25

// ---------------- device scratch (no runtime allocation allowed) ----------------
__device__ float g_psq[PP];
__device__ float g_v1[PP];
__device__ float g_v2[PP];
__device__ float g_PW[PP * DD];        // protos @ W          [P, D]
__device__ float g_M[PP * PP];         // (protos@W) @ protosT [P, P]
__device__ int   g_labels[BB];
__device__ float g_lam[BB];
__device__ float g_mixed[(size_t)BB * DD];
__device__ float g_logits[(size_t)BB * PP];  // leaky_relu(proto logits)

// =================================================================
// prep: p_sq[p], v1[p] = protos[p]·lin_w[0:D], v2[p] = protos[p]·lin_w[D:2D]
// =================================================================
__global__ __launch_bounds__(256) void prep_kernel(
    const float* __restrict__ protos, const float* __restrict__ lin_w)
{
    int p = blockIdx.x;
    int t = threadIdx.x;
    float sq = 0.f, a1 = 0.f, a2 = 0.f;
    const float* row = protos + (size_t)p * DD;
    for (int k = t; k < DD; k += 256) {
        float v = row[k];
        sq = fmaf(v, v, sq);
        a1 = fmaf(v, lin_w[k], a1);
        a2 = fmaf(v, lin_w[DD + k], a2);
    }
    __shared__ float s1[256], s2[256], s3[256];
    s1[t] = sq; s2[t] = a1; s3[t] = a2;
    __syncthreads();
    for (int off = 128; off; off >>= 1) {
        if (t < off) { s1[t] += s1[t + off]; s2[t] += s2[t + off]; s3[t] += s3[t + off]; }
        __syncthreads();
    }
    if (t == 0) { g_psq[p] = s1[0]; g_v1[p] = s2[0]; g_v2[p] = s3[0]; }
}

// =================================================================
// Generic 128x128x8 fp32 SGEMM, 256 threads, 8x8 micro-tile, double-buffered.
// BNT=true : B is [N,K] row-major (C = A * B^T)
// BNT=false: B is [K,N] row-major (C = A * B)
// LEAKY: epilogue adds bias[col] then leaky_relu(0.01)
// =================================================================
template <bool BNT, bool LEAKY>
__global__ __launch_bounds__(256)
void sgemm_kernel(const float* __restrict__ A, const float* __restrict__ B,
                  float* __restrict__ C, const float* __restrict__ bias,
                  int M, int N, int K)
{
    __shared__ float As[2][8][128];
    __shared__ float Bs[2][8][128];

    const int tid = threadIdx.x;
    const int tx = tid & 15;
    const int ty = tid >> 4;
    const int row0 = blockIdx.y * 128;
    const int col0 = blockIdx.x * 128;

    // A (and B when NT) load mapping: one float4 of K per thread
    const int a_r = tid >> 1;          // 0..127
    const int a_k = (tid & 1) * 4;     // 0 or 4
    // B NN mapping
    const int b_k = tid >> 5;          // 0..7
    const int b_n = (tid & 31) * 4;    // 0..124

    float acc[8][8];
#pragma unroll
    for (int i = 0; i < 8; i++)
#pragma unroll
        for (int j = 0; j < 8; j++) acc[i][j] = 0.f;

    float4 ra, rb;
    auto loadG = [&](int k0) {
        ra = *reinterpret_cast<const float4*>(&A[(size_t)(row0 + a_r) * K + k0 + a_k]);
        if (BNT) rb = *reinterpret_cast<const float4*>(&B[(size_t)(col0 + a_r) * K + k0 + a_k]);
        else     rb = *reinterpret_cast<const float4*>(&B[(size_t)(k0 + b_k) * N + col0 + b_n]);
    };
    auto storeS = [&](int buf) {
        As[buf][a_k + 0][a_r] = ra.x; As[buf][a_k + 1][a_r] = ra.y;
        As[buf][a_k + 2][a_r] = ra.z; As[buf][a_k + 3][a_r] = ra.w;
        if (BNT) {
            Bs[buf][a_k + 0][a_r] = rb.x; Bs[buf][a_k + 1][a_r] = rb.y;
            Bs[buf][a_k + 2][a_r] = rb.z; Bs[buf][a_k + 3][a_r] = rb.w;
        } else {
            *reinterpret_cast<float4*>(&Bs[buf][b_k][b_n]) = rb;
        }
    };

    loadG(0);
    storeS(0);
    __syncthreads();

    const int nk = K >> 3;
    for (int kt = 0; kt < nk; kt++) {
        int cur = kt & 1;
        if (kt + 1 < nk) loadG((kt + 1) << 3);
#pragma unroll
        for (int kk = 0; kk < 8; kk++) {
            float af[8], bf[8];
#pragma unroll
            for (int i = 0; i < 8; i++) af[i] = As[cur][kk][ty * 8 + i];
#pragma unroll
            for (int j = 0; j < 8; j++) bf[j] = Bs[cur][kk][tx * 8 + j];
#pragma unroll
            for (int i = 0; i < 8; i++)
#pragma unroll
                for (int j = 0; j < 8; j++)
                    acc[i][j] = fmaf(af[i], bf[j], acc[i][j]);
        }
        if (kt + 1 < nk) storeS(cur ^ 1);
        __syncthreads();
    }

#pragma unroll
    for (int i = 0; i < 8; i++) {
        int r = row0 + ty * 8 + i;
#pragma unroll
        for (int j = 0; j < 8; j++) {
            int c = col0 + tx * 8 + j;
            float v = acc[i][j];
            if (LEAKY) {
                v += bias[c];
                v = v > 0.f ? v : 0.01f * v;
            }
            C[(size_t)r * N + c] = v;
        }
    }
}

// =================================================================
// Distance + argmin: for 128 rows, loop over all P prototype column tiles,
// track argmin_p of (p_sq[p] - 2 * patient·protos[p]). Equivalent ordering
// to argmin of sqrt(max(e_sq + p_sq - 2*dot, 0)).
// =================================================================
__global__ __launch_bounds__(256)
void dist_argmin_kernel(const float* __restrict__ A /*patient [B,D]*/,
                        const float* __restrict__ Bm /*protos [P,D]*/)
{
    __shared__ float As[2][8][128];
    __shared__ float Bs[2][8][128];
    __shared__ float rv[128][16];
    __shared__ int   ri[128][16];

    const int tid = threadIdx.x;
    const int tx = tid & 15;
    const int ty = tid >> 4;
    const int row0 = blockIdx.x * 128;

    const int a_r = tid >> 1;
    const int a_k = (tid & 1) * 4;

    float minv[8];
    int   mini[8];
#pragma unroll
    for (int i = 0; i < 8; i++) { minv[i] = 3.4e38f; mini[i] = 0; }

    for (int ct = 0; ct < PP / 128; ct++) {
        const int col0 = ct * 128;
        float acc[8][8];
#pragma unroll
        for (int i = 0; i < 8; i++)
#pragma unroll
            for (int j = 0; j < 8; j++) acc[i][j] = 0.f;

        float4 ra, rb;
        auto loadG = [&](int k0) {
            ra = *reinterpret_cast<const float4*>(&A[(size_t)(row0 + a_r) * DD + k0 + a_k]);
            rb = *reinterpret_cast<const float4*>(&Bm[(size_t)(col0 + a_r) * DD + k0 + a_k]);
        };
        auto storeS = [&](int buf) {
            As[buf][a_k + 0][a_r] = ra.x; As[buf][a_k + 1][a_r] = ra.y;
            As[buf][a_k + 2][a_r] = ra.z; As[buf][a_k + 3][a_r] = ra.w;
            Bs[buf][a_k + 0][a_r] = rb.x; Bs[buf][a_k + 1][a_r] = rb.y;
            Bs[buf][a_k + 2][a_r] = rb.z; Bs[buf][a_k + 3][a_r] = rb.w;
        };

        loadG(0);
        storeS(0);
        __syncthreads();
        const int nk = DD >> 3;
        for (int kt = 0; kt < nk; kt++) {
            int cur = kt & 1;
            if (kt + 1 < nk) loadG((kt + 1) << 3);
#pragma unroll
            for (int kk = 0; kk < 8; kk++) {
                float af[8], bf[8];
#pragma unroll
                for (int i = 0; i < 8; i++) af[i] = As[cur][kk][ty * 8 + i];
#pragma unroll
                for (int j = 0; j < 8; j++) bf[j] = Bs[cur][kk][tx * 8 + j];
#pragma unroll
                for (int i = 0; i < 8; i++)
#pragma unroll
                    for (int j = 0; j < 8; j++)
                        acc[i][j] = fmaf(af[i], bf[j], acc[i][j]);
            }
            if (kt + 1 < nk) storeS(cur ^ 1);
            __syncthreads();
        }

        float pq[8];
#pragma unroll
        for (int j = 0; j < 8; j++) pq[j] = g_psq[col0 + tx * 8 + j];
#pragma unroll
        for (int i = 0; i < 8; i++) {
#pragma unroll
            for (int j = 0; j < 8; j++) {
                float s = pq[j] - 2.f * acc[i][j];
                int c = col0 + tx * 8 + j;
                if (s < minv[i]) { minv[i] = s; mini[i] = c; }
            }
        }
        __syncthreads();   // before reusing shared tiles next iteration
    }

#pragma unroll
    for (int i = 0; i < 8; i++) {
        rv[ty * 8 + i][tx] = minv[i];
        ri[ty * 8 + i][tx] = mini[i];
    }
    __syncthreads();
    if (tid < 128) {
        float bv = rv[tid][0];
        int bi = ri[tid][0];
#pragma unroll
        for (int t = 1; t < 16; t++) {
            float v = rv[tid][t];
            int id = ri[tid][t];
            if (v < bv || (v == bv && id < bi)) { bv = v; bi = id; }
        }
        g_labels[row0 + tid] = bi;
    }
}

// =================================================================
// lam[b] = sigmoid(M[la,lb] + bilinear_b + v1[la] + v2[lb])
// =================================================================
__global__ __launch_bounds__(256)
void lam_kernel(const int* __restrict__ index, const float* __restrict__ bilinear_b)
{
    int b = blockIdx.x * 256 + threadIdx.x;
    if (b >= BB) return;
    int la = g_labels[b];
    int lb = g_labels[index[b]];
    float s = g_M[(size_t)la * PP + lb] + bilinear_b[0] + g_v1[la] + g_v2[lb];
    g_lam[b] = 1.f / (1.f + expf(-s));
}

// =================================================================
// mixed[b,:] = lam[b]*patient[b,:] + (1-lam[b])*patient[index[b],:]
// =================================================================
__global__ __launch_bounds__(256)
void mix_kernel(const float* __restrict__ patient, const int* __restrict__ index)
{
    int b = blockIdx.x;
    float lam = g_lam[b];
    float oml = 1.f - lam;
    int ib = index[b];
    const float4* xa = reinterpret_cast<const float4*>(patient + (size_t)b * DD);
    const float4* xb = reinterpret_cast<const float4*>(patient + (size_t)ib * DD);
    float4* o = reinterpret_cast<float4*>(g_mixed + (size_t)b * DD);
    int t = threadIdx.x;   // 256 threads * float4 = 1024 floats
    float4 a = xa[t], c = xb[t];
    float4 r;
    r.x = lam * a.x + oml * c.x;
    r.y = lam * a.y + oml * c.y;
    r.z = lam * a.z + oml * c.z;
    r.w = lam * a.w + oml * c.w;
    o[t] = r;
}

// =================================================================
// class head: out[b,o] = sum_p g_logits[b,p] * cw[o,p] + cb[o]
// (g_logits already has leaky applied). One warp per row.
// =================================================================
__global__ __launch_bounds__(256)
void class_kernel(const float* __restrict__ cw, const float* __restrict__ cb,
                  float* __restrict__ out)
{
    int gw = (blockIdx.x * 256 + threadIdx.x) >> 5;   // global warp = row
    int lane = threadIdx.x & 31;
    if (gw >= BB) return;
    const float* lrow = g_logits + (size_t)gw * PP;
    float acc[OUTC];
#pragma unroll
    for (int o = 0; o < OUTC; o++) acc[o] = 0.f;
    for (int p = lane; p < PP; p += 32) {
        float v = lrow[p];
#pragma unroll
        for (int o = 0; o < OUTC; o++)
            acc[o] = fmaf(v, cw[o * PP + p], acc[o]);
    }
#pragma unroll
    for (int o = 0; o < OUTC; o++) {
        for (int off = 16; off; off >>= 1)
            acc[o] += __shfl_down_sync(0xffffffffu, acc[o], off);
    }
    if (lane == 0) {
#pragma unroll
        for (int o = 0; o < OUTC; o++)
            out[(size_t)gw * OUTC + o] = acc[o] + cb[o];
    }
}

// =================================================================
// launch
// =================================================================
extern "C" void kernel_launch(void* const* d_in, const int* in_sizes, int n_in,
                              void* d_out, int out_size)
{
    const float* patient    = (const float*)d_in[0];  // [B,D]
    const float* protos     = (const float*)d_in[1];  // [P,D]
    const int*   index      = (const int*)  d_in[2];  // [B]
    const float* bilinear_w = (const float*)d_in[3];  // [1,D,D]
    const float* bilinear_b = (const float*)d_in[4];  // [1]
    const float* lin_w      = (const float*)d_in[5];  // [1,2D]
    const float* proto_fc_w = (const float*)d_in[6];  // [P,D]
    const float* proto_fc_b = (const float*)d_in[7];  // [P]
    const float* class_fc_w = (const float*)d_in[8];  // [OUT,P]
    const float* class_fc_b = (const float*)d_in[9];  // [OUT]
    float* out = (float*)d_out;

    float* pPW;     cudaGetSymbolAddress((void**)&pPW, g_PW);
    float* pM;      cudaGetSymbolAddress((void**)&pM, g_M);
    float* pMixed;  cudaGetSymbolAddress((void**)&pMixed, g_mixed);
    float* pLogits; cudaGetSymbolAddress((void**)&pLogits, g_logits);

    // 1. per-prototype scalars
    prep_kernel<<<PP, 256>>>(protos, lin_w);

    // 2. PW = protos @ W   (NN: W is [D,D] k-major)
    {
        dim3 grid(DD / 128, PP / 128);
        sgemm_kernel<false, false><<<grid, 256>>>(protos, bilinear_w, pPW, nullptr, PP, DD, DD);
    }
    // 3. M = PW @ protos^T (NT)
    {
        dim3 grid(PP / 128, PP / 128);
        sgemm_kernel<true, false><<<grid, 256>>>(pPW, protos, pM, nullptr, PP, PP, DD);
    }
    // 4. nearest prototype per patient
    dist_argmin_kernel<<<BB / 128, 256>>>(patient, protos);

    // 5. lam
    lam_kernel<<<BB / 256, 256>>>(index, bilinear_b);

    // 6. mixed embedding
    mix_kernel<<<BB, 256>>>(patient, index);

    // 7. proto logits (+bias, leaky) : mixed @ proto_fc_w^T  (NT)
    {
        dim3 grid(PP / 128, BB / 128);
        sgemm_kernel<true, true><<<grid, 256>>>(pMixed, proto_fc_w, pLogits, proto_fc_b, BB, PP, DD);
    }
    // 8. class head
    class_kernel<<<BB / 8, 256>>>(class_fc_w, class_fc_b, out);
}

// round 3
// speedup vs baseline: 2.7885x; 2.7885x over previous
#include <cuda_runtime.h>
#include <cuda_bf16.h>
#include <math.h>
#include <stdint.h>

#define BB   16384
#define DD   1024
#define PP   1024
#define OUTC 25
#define NTIL 8
#define MARGIN 0.05f
#define NSTAGE 3
#define STAGE_BYTES 32768            // 4 tiles * 8KB
#define SM_MERGE (NSTAGE * STAGE_BYTES)
#define SM_TOTAL (SM_MERGE + 128 * 2 * 16)

// ---------------- device scratch ----------------
__device__ float g_psq[PP];
__device__ float g_v1[PP];
__device__ float g_v2[PP];
__device__ float g_PW[PP * DD];
__device__ int   g_labels[BB];
__device__ float g_lam[BB];
__device__ float g_logits[(size_t)BB * PP];
__device__ float4 g_top2[(size_t)BB * NTIL];

__device__ __nv_bfloat16 g_pa_hi[(size_t)BB * DD];
__device__ __nv_bfloat16 g_pa_lo[(size_t)BB * DD];
__device__ __nv_bfloat16 g_pr_hi[(size_t)PP * DD];
__device__ __nv_bfloat16 g_pr_lo[(size_t)PP * DD];
__device__ __nv_bfloat16 g_fc_hi[(size_t)PP * DD];
__device__ __nv_bfloat16 g_fc_lo[(size_t)PP * DD];
__device__ __nv_bfloat16 g_mx_hi[(size_t)BB * DD];
__device__ __nv_bfloat16 g_mx_lo[(size_t)BB * DD];

// ---------------- helpers ----------------
__device__ __forceinline__ uint32_t smem_u32(const void* p) {
    uint32_t a;
    asm("{ .reg .u64 t; cvta.to.shared.u64 t, %1; cvt.u32.u64 %0, t; }" : "=r"(a) : "l"(p));
    return a;
}
__device__ __forceinline__ void ldsm4(uint32_t r[4], uint32_t addr) {
    asm volatile("ldmatrix.sync.aligned.m8n8.x4.shared.b16 {%0,%1,%2,%3}, [%4];"
                 : "=r"(r[0]), "=r"(r[1]), "=r"(r[2]), "=r"(r[3]) : "r"(addr));
}
__device__ __forceinline__ void mma16816(float c[4], const uint32_t a[4],
                                         uint32_t b0, uint32_t b1) {
    asm volatile("mma.sync.aligned.m16n8k16.row.col.f32.bf16.bf16.f32 "
                 "{%0,%1,%2,%3}, {%4,%5,%6,%7}, {%8,%9}, {%0,%1,%2,%3};"
                 : "+f"(c[0]), "+f"(c[1]), "+f"(c[2]), "+f"(c[3])
                 : "r"(a[0]), "r"(a[1]), "r"(a[2]), "r"(a[3]), "r"(b0), "r"(b1));
}
__device__ __forceinline__ void top2_upd(float s, int idx, float& v1, int& i1,
                                         float& v2, int& i2) {
    if (s < v1 || (s == v1 && idx < i1)) { v2 = v1; i2 = i1; v1 = s; i1 = idx; }
    else if (s < v2 || (s == v2 && idx < i2)) { v2 = s; i2 = idx; }
}
__device__ __forceinline__ void top2_merge(float w1, int j1, float w2, int j2,
                                           float& v1, int& i1, float& v2, int& i2) {
    top2_upd(w1, j1, v1, i1, v2, i2);
    top2_upd(w2, j2, v1, i1, v2, i2);
}

// =================================================================
// prep: p_sq, v1, v2
// =================================================================
__global__ __launch_bounds__(256) void prep_kernel(
    const float* __restrict__ protos, const float* __restrict__ lin_w)
{
    int p = blockIdx.x, t = threadIdx.x;
    float sq = 0.f, a1 = 0.f, a2 = 0.f;
    const float* row = protos + (size_t)p * DD;
    for (int k = t; k < DD; k += 256) {
        float v = row[k];
        sq = fmaf(v, v, sq);
        a1 = fmaf(v, lin_w[k], a1);
        a2 = fmaf(v, lin_w[DD + k], a2);
    }
    __shared__ float s1[256], s2[256], s3[256];
    s1[t] = sq; s2[t] = a1; s3[t] = a2;
    __syncthreads();
    for (int off = 128; off; off >>= 1) {
        if (t < off) { s1[t] += s1[t+off]; s2[t] += s2[t+off]; s3[t] += s3[t+off]; }
        __syncthreads();
    }
    if (t == 0) { g_psq[p] = s1[0]; g_v1[p] = s2[0]; g_v2[p] = s3[0]; }
}

// =================================================================
// split fp32 -> bf16 hi + lo
// =================================================================
__global__ __launch_bounds__(256) void split_kernel(
    const float* __restrict__ src, __nv_bfloat16* __restrict__ hi,
    __nv_bfloat16* __restrict__ lo, int n4)
{
    int i = blockIdx.x * 256 + threadIdx.x;
    if (i >= n4) return;
    float4 v = reinterpret_cast<const float4*>(src)[i];
    __nv_bfloat16 h0 = __float2bfloat16(v.x), h1 = __float2bfloat16(v.y);
    __nv_bfloat16 h2 = __float2bfloat16(v.z), h3 = __float2bfloat16(v.w);
    __nv_bfloat16 l0 = __float2bfloat16(v.x - __bfloat162float(h0));
    __nv_bfloat16 l1 = __float2bfloat16(v.y - __bfloat162float(h1));
    __nv_bfloat16 l2 = __float2bfloat16(v.z - __bfloat162float(h2));
    __nv_bfloat16 l3 = __float2bfloat16(v.w - __bfloat162float(h3));
    __nv_bfloat162 hh0 = {h0, h1}, hh1 = {h2, h3}, ll0 = {l0, l1}, ll1 = {l2, l3};
    reinterpret_cast<__nv_bfloat162*>(hi)[2*i]   = hh0;
    reinterpret_cast<__nv_bfloat162*>(hi)[2*i+1] = hh1;
    reinterpret_cast<__nv_bfloat162*>(lo)[2*i]   = ll0;
    reinterpret_cast<__nv_bfloat162*>(lo)[2*i+1] = ll1;
}

// =================================================================
// fp32 SIMT SGEMM (NN) for PW = protos @ W
// =================================================================
__global__ __launch_bounds__(256)
void sgemm_nn_kernel(const float* __restrict__ A, const float* __restrict__ B,
                     float* __restrict__ C, int M, int N, int K)
{
    __shared__ float As[2][8][128];
    __shared__ float Bs[2][8][128];
    const int tid = threadIdx.x;
    const int tx = tid & 15, ty = tid >> 4;
    const int row0 = blockIdx.y * 128, col0 = blockIdx.x * 128;
    const int a_r = tid >> 1, a_k = (tid & 1) * 4;
    const int b_k = tid >> 5, b_n = (tid & 31) * 4;

    float acc[8][8];
#pragma unroll
    for (int i = 0; i < 8; i++)
#pragma unroll
        for (int j = 0; j < 8; j++) acc[i][j] = 0.f;

    float4 ra, rb;
    auto loadG = [&](int k0) {
        ra = *reinterpret_cast<const float4*>(&A[(size_t)(row0 + a_r) * K + k0 + a_k]);
        rb = *reinterpret_cast<const float4*>(&B[(size_t)(k0 + b_k) * N + col0 + b_n]);
    };
    auto storeS = [&](int buf) {
        As[buf][a_k+0][a_r] = ra.x; As[buf][a_k+1][a_r] = ra.y;
        As[buf][a_k+2][a_r] = ra.z; As[buf][a_k+3][a_r] = ra.w;
        *reinterpret_cast<float4*>(&Bs[buf][b_k][b_n]) = rb;
    };
    loadG(0); storeS(0);
    __syncthreads();
    const int nk = K >> 3;
    for (int kt = 0; kt < nk; kt++) {
        int cur = kt & 1;
        if (kt + 1 < nk) loadG((kt + 1) << 3);
#pragma unroll
        for (int kk = 0; kk < 8; kk++) {
            float af[8], bf[8];
#pragma unroll
            for (int i = 0; i < 8; i++) af[i] = As[cur][kk][ty*8+i];
#pragma unroll
            for (int j = 0; j < 8; j++) bf[j] = Bs[cur][kk][tx*8+j];
#pragma unroll
            for (int i = 0; i < 8; i++)
#pragma unroll
                for (int j = 0; j < 8; j++) acc[i][j] = fmaf(af[i], bf[j], acc[i][j]);
        }
        if (kt + 1 < nk) storeS(cur ^ 1);
        __syncthreads();
    }
#pragma unroll
    for (int i = 0; i < 8; i++)
#pragma unroll
        for (int j = 0; j < 8; j++)
            C[(size_t)(row0 + ty*8 + i) * N + col0 + tx*8 + j] = acc[i][j];
}

// =================================================================
// HMMA split-bf16 GEMM (mma.sync m16n8k16), 128x128 tile, BK=32,
// 3-stage cp.async pipeline. 3 passes (hh, hl, lh) per k16.
// MODE 0: dist epilogue -> per-tile top2 into g_top2
// MODE 1: bias + leaky -> outp [*, PP]
// =================================================================
template <int MODE>
__global__ __launch_bounds__(256)
void hmma_gemm_kernel(const __nv_bfloat16* __restrict__ Ahi, const __nv_bfloat16* __restrict__ Alo,
                      const __nv_bfloat16* __restrict__ Bhi, const __nv_bfloat16* __restrict__ Blo,
                      const float* __restrict__ bias, float* __restrict__ outp)
{
    extern __shared__ char smem[];
    const uint32_t sb = smem_u32(smem);
    const int tid = threadIdx.x;
    const int lane = tid & 31;
    const int w = tid >> 5;
    const int wm = w & 3;          // 4 warps along M (32 rows each)
    const int wn = w >> 2;         // 2 warps along N (64 cols each)
    const int row0 = blockIdx.y * 128;
    const int col0 = blockIdx.x * 128;

    // ldmatrix per-lane row/chunk decomposition
    const int q  = lane >> 3;
    const int lr = lane & 7;
    const int achk = q >> 1;       // A: extra k-chunk bit
    const int bchk = q & 1;        // B: extra k-chunk bit
    int arow[2], brow[4];
#pragma unroll
    for (int mi = 0; mi < 2; mi++) arow[mi] = wm*32 + mi*16 + ((q & 1) << 3) + lr;
#pragma unroll
    for (int ng = 0; ng < 4; ng++) brow[ng] = wn*64 + ng*16 + ((q >> 1) << 3) + lr;

    float c[2][8][4];
#pragma unroll
    for (int mi = 0; mi < 2; mi++)
#pragma unroll
        for (int nf = 0; nf < 8; nf++)
#pragma unroll
            for (int j = 0; j < 4; j++) c[mi][nf][j] = 0.f;

    // cp.async issue for one stage / one k-chunk (BK=32)
    auto issue = [&](int st, int kt) {
        const int k0 = kt << 5;
        const uint32_t sbase = sb + st * STAGE_BYTES;
#pragma unroll
        for (int it = 0; it < 8; it++) {
            int ch = it * 256 + tid;
            int t = ch >> 9;              // tile 0..3 (constant per it pair)
            int within = ch & 511;
            int r = within >> 2;
            int cc = within & 3;
            const __nv_bfloat16* src = (t == 0) ? Ahi : (t == 1) ? Alo : (t == 2) ? Bhi : Blo;
            int rbase = (t < 2) ? row0 : col0;
            const void* g = src + (size_t)(rbase + r) * DD + k0 + cc * 8;
            uint32_t s = sbase + t * 8192 + r * 64 + ((cc ^ ((r >> 1) & 3)) << 4);
            asm volatile("cp.async.cg.shared.global [%0], [%1], 16;" :: "r"(s), "l"(g));
        }
        asm volatile("cp.async.commit_group;" ::: "memory");
    };

    auto compute = [&](int st) {
        const uint32_t sbase = sb + st * STAGE_BYTES;
#pragma unroll
        for (int ks = 0; ks < 2; ks++) {
            uint32_t ah[2][4], al[2][4], bh[4][4], bl[4][4];
#pragma unroll
            for (int mi = 0; mi < 2; mi++) {
                uint32_t ra = sbase + arow[mi] * 64 +
                              ((((ks << 1) | achk) ^ ((arow[mi] >> 1) & 3)) << 4);
                ldsm4(ah[mi], ra);
                ldsm4(al[mi], ra + 8192);
            }
#pragma unroll
            for (int ng = 0; ng < 4; ng++) {
                uint32_t rb = sbase + 2 * 8192 + brow[ng] * 64 +
                              ((((ks << 1) | bchk) ^ ((brow[ng] >> 1) & 3)) << 4);
                ldsm4(bh[ng], rb);
                ldsm4(bl[ng], rb + 8192);
            }
#pragma unroll
            for (int mi = 0; mi < 2; mi++)
#pragma unroll
                for (int ng = 0; ng < 4; ng++)
#pragma unroll
                    for (int h = 0; h < 2; h++) {
                        int nf = ng * 2 + h;
                        mma16816(c[mi][nf], ah[mi], bh[ng][h*2], bh[ng][h*2+1]); // hi*hi
                        mma16816(c[mi][nf], ah[mi], bl[ng][h*2], bl[ng][h*2+1]); // hi*lo
                        mma16816(c[mi][nf], al[mi], bh[ng][h*2], bh[ng][h*2+1]); // lo*hi
                    }
        }
    };

    const int NK = DD / 32;
    issue(0, 0);
    issue(1, 1);
    for (int kt = 0; kt < NK; kt++) {
        asm volatile("cp.async.wait_group 1;" ::: "memory");
        __syncthreads();
        compute(kt % NSTAGE);
        if (kt + 2 < NK) issue((kt + 2) % NSTAGE, kt + 2);
        __syncthreads();
    }

    if (MODE == 0) {
        float4* mbuf = reinterpret_cast<float4*>(smem + SM_MERGE);
#pragma unroll
        for (int mi = 0; mi < 2; mi++)
#pragma unroll
            for (int rh = 0; rh < 2; rh++) {
                int lrow_ = wm*32 + mi*16 + rh*8 + (lane >> 2);
                float v1 = 3.4e38f, v2 = 3.4e38f;
                int i1 = 0, i2 = 0;
#pragma unroll
                for (int nf = 0; nf < 8; nf++) {
                    int col = col0 + wn*64 + nf*8 + ((lane & 3) << 1);
                    float s0 = bias[col]     - 2.f * c[mi][nf][rh*2];
                    float s1 = bias[col + 1] - 2.f * c[mi][nf][rh*2+1];
                    top2_upd(s0, col,     v1, i1, v2, i2);
                    top2_upd(s1, col + 1, v1, i1, v2, i2);
                }
#pragma unroll
                for (int d = 1; d <= 2; d <<= 1) {
                    float w1 = __shfl_xor_sync(0xffffffffu, v1, d);
                    float w2 = __shfl_xor_sync(0xffffffffu, v2, d);
                    int   j1 = __shfl_xor_sync(0xffffffffu, i1, d);
                    int   j2 = __shfl_xor_sync(0xffffffffu, i2, d);
                    top2_merge(w1, j1, w2, j2, v1, i1, v2, i2);
                }
                if ((lane & 3) == 0)
                    mbuf[lrow_ * 2 + wn] =
                        make_float4(v1, __int_as_float(i1), v2, __int_as_float(i2));
            }
        __syncthreads();
        if (tid < 128) {
            float4 a = mbuf[tid * 2 + 0];
            float4 b = mbuf[tid * 2 + 1];
            float v1 = a.x, v2 = a.z;
            int i1 = __float_as_int(a.y), i2 = __float_as_int(a.w);
            top2_merge(b.x, __float_as_int(b.y), b.z, __float_as_int(b.w), v1, i1, v2, i2);
            reinterpret_cast<float4*>(outp)[(size_t)(row0 + tid) * NTIL + blockIdx.x] =
                make_float4(v1, __int_as_float(i1), v2, __int_as_float(i2));
        }
    } else {
#pragma unroll
        for (int mi = 0; mi < 2; mi++)
#pragma unroll
            for (int rh = 0; rh < 2; rh++) {
                int r = row0 + wm*32 + mi*16 + rh*8 + (lane >> 2);
#pragma unroll
                for (int nf = 0; nf < 8; nf++) {
                    int col = col0 + wn*64 + nf*8 + ((lane & 3) << 1);
                    float v0 = c[mi][nf][rh*2]   + bias[col];
                    float v1 = c[mi][nf][rh*2+1] + bias[col + 1];
                    v0 = v0 > 0.f ? v0 : 0.01f * v0;
                    v1 = v1 > 0.f ? v1 : 0.01f * v1;
                    float2 o = {v0, v1};
                    *reinterpret_cast<float2*>(&outp[(size_t)r * PP + col]) = o;
                }
            }
    }
}

// =================================================================
// merge per-tile top2 + exact rescue for near-ties
// =================================================================
__global__ __launch_bounds__(256)
void argmin_reduce_kernel(const float* __restrict__ patient, const float* __restrict__ protos)
{
    int w = (blockIdx.x * 256 + threadIdx.x) >> 5;
    int lane = threadIdx.x & 31;
    if (w >= BB) return;
    float v1 = 0.f, v2 = 0.f; int i1 = 0, i2 = 0;
    if (lane == 0) {
        v1 = 3.4e38f; v2 = 3.4e38f;
        for (int t = 0; t < NTIL; t++) {
            float4 qd = g_top2[(size_t)w * NTIL + t];
            top2_merge(qd.x, __float_as_int(qd.y), qd.z, __float_as_int(qd.w), v1, i1, v2, i2);
        }
    }
    v1 = __shfl_sync(0xffffffffu, v1, 0);
    v2 = __shfl_sync(0xffffffffu, v2, 0);
    i1 = __shfl_sync(0xffffffffu, i1, 0);
    i2 = __shfl_sync(0xffffffffu, i2, 0);
    if (v2 - v1 >= MARGIN) {
        if (lane == 0) g_labels[w] = i1;
        return;
    }
    const float* x  = patient + (size_t)w * DD;
    const float* pA = protos + (size_t)i1 * DD;
    const float* pB = protos + (size_t)i2 * DD;
    double da = 0.0, db = 0.0;
    for (int k = lane; k < DD; k += 32) {
        double xv = x[k];
        da += xv * (double)pA[k];
        db += xv * (double)pB[k];
    }
#pragma unroll
    for (int off = 16; off; off >>= 1) {
        da += __shfl_down_sync(0xffffffffu, da, off);
        db += __shfl_down_sync(0xffffffffu, db, off);
    }
    if (lane == 0) {
        double sA = (double)g_psq[i1] - 2.0 * da;
        double sB = (double)g_psq[i2] - 2.0 * db;
        bool pickA = (sA < sB) || (sA == sB && i1 < i2);
        g_labels[w] = pickA ? i1 : i2;
    }
}

// =================================================================
// lam[b] = sigmoid(PW[la].protos[lb] + bil_b + v1[la] + v2[lb])
// =================================================================
__global__ __launch_bounds__(256)
void lam_kernel(const int* __restrict__ index, const float* __restrict__ bilinear_b,
                const float* __restrict__ protos)
{
    int w = (blockIdx.x * 256 + threadIdx.x) >> 5;
    int lane = threadIdx.x & 31;
    if (w >= BB) return;
    int la = g_labels[w];
    int lb = g_labels[index[w]];
    const float4* a = reinterpret_cast<const float4*>(g_PW + (size_t)la * DD);
    const float4* p = reinterpret_cast<const float4*>(protos + (size_t)lb * DD);
    float acc = 0.f;
    for (int k = lane; k < DD / 4; k += 32) {
        float4 u = a[k], v = p[k];
        acc = fmaf(u.x, v.x, acc); acc = fmaf(u.y, v.y, acc);
        acc = fmaf(u.z, v.z, acc); acc = fmaf(u.w, v.w, acc);
    }
#pragma unroll
    for (int off = 16; off; off >>= 1) acc += __shfl_down_sync(0xffffffffu, acc, off);
    if (lane == 0) {
        float s = acc + bilinear_b[0] + g_v1[la] + g_v2[lb];
        g_lam[w] = 1.f / (1.f + expf(-s));
    }
}

// =================================================================
// mixed = lam*x + (1-lam)*x[index]; emit bf16 hi/lo directly
// =================================================================
__global__ __launch_bounds__(256)
void mix_kernel(const float* __restrict__ patient, const int* __restrict__ index)
{
    int b = blockIdx.x;
    float lam = g_lam[b], oml = 1.f - lam;
    int ib = index[b];
    int t = threadIdx.x;
    float4 a = reinterpret_cast<const float4*>(patient + (size_t)b * DD)[t];
    float4 c = reinterpret_cast<const float4*>(patient + (size_t)ib * DD)[t];
    float m0 = lam * a.x + oml * c.x, m1 = lam * a.y + oml * c.y;
    float m2 = lam * a.z + oml * c.z, m3 = lam * a.w + oml * c.w;
    __nv_bfloat16 h0 = __float2bfloat16(m0), h1 = __float2bfloat16(m1);
    __nv_bfloat16 h2 = __float2bfloat16(m2), h3 = __float2bfloat16(m3);
    __nv_bfloat16 l0 = __float2bfloat16(m0 - __bfloat162float(h0));
    __nv_bfloat16 l1 = __float2bfloat16(m1 - __bfloat162float(h1));
    __nv_bfloat16 l2 = __float2bfloat16(m2 - __bfloat162float(h2));
    __nv_bfloat16 l3 = __float2bfloat16(m3 - __bfloat162float(h3));
    size_t o = (size_t)b * (DD / 2) + 2 * t;
    __nv_bfloat162 hh0 = {h0, h1}, hh1 = {h2, h3}, ll0 = {l0, l1}, ll1 = {l2, l3};
    reinterpret_cast<__nv_bfloat162*>(g_mx_hi)[o]     = hh0;
    reinterpret_cast<__nv_bfloat162*>(g_mx_hi)[o + 1] = hh1;
    reinterpret_cast<__nv_bfloat162*>(g_mx_lo)[o]     = ll0;
    reinterpret_cast<__nv_bfloat162*>(g_mx_lo)[o + 1] = ll1;
}

// =================================================================
// class head (warp per row)
// =================================================================
__global__ __launch_bounds__(256)
void class_kernel(const float* __restrict__ cw, const float* __restrict__ cb,
                  float* __restrict__ out)
{
    int gw = (blockIdx.x * 256 + threadIdx.x) >> 5;
    int lane = threadIdx.x & 31;
    if (gw >= BB) return;
    const float* lrow = g_logits + (size_t)gw * PP;
    float acc[OUTC];
#pragma unroll
    for (int o = 0; o < OUTC; o++) acc[o] = 0.f;
    for (int p = lane; p < PP; p += 32) {
        float v = lrow[p];
#pragma unroll
        for (int o = 0; o < OUTC; o++) acc[o] = fmaf(v, cw[o * PP + p], acc[o]);
    }
#pragma unroll
    for (int o = 0; o < OUTC; o++)
        for (int off = 16; off; off >>= 1)
            acc[o] += __shfl_down_sync(0xffffffffu, acc[o], off);
    if (lane == 0)
#pragma unroll
        for (int o = 0; o < OUTC; o++)
            out[(size_t)gw * OUTC + o] = acc[o] + cb[o];
}

// =================================================================
// launch
// =================================================================
extern "C" void kernel_launch(void* const* d_in, const int* in_sizes, int n_in,
                              void* d_out, int out_size)
{
    const float* patient    = (const float*)d_in[0];
    const float* protos     = (const float*)d_in[1];
    const int*   index      = (const int*)  d_in[2];
    const float* bilinear_w = (const float*)d_in[3];
    const float* bilinear_b = (const float*)d_in[4];
    const float* lin_w      = (const float*)d_in[5];
    const float* proto_fc_w = (const float*)d_in[6];
    const float* proto_fc_b = (const float*)d_in[7];
    const float* class_fc_w = (const float*)d_in[8];
    const float* class_fc_b = (const float*)d_in[9];
    float* out = (float*)d_out;

    float *pPW, *pPsq, *pLogits;
    float4* pTop2;
    __nv_bfloat16 *pPaHi, *pPaLo, *pPrHi, *pPrLo, *pFcHi, *pFcLo, *pMxHi, *pMxLo;
    cudaGetSymbolAddress((void**)&pPW, g_PW);
    cudaGetSymbolAddress((void**)&pPsq, g_psq);
    cudaGetSymbolAddress((void**)&pLogits, g_logits);
    cudaGetSymbolAddress((void**)&pTop2, g_top2);
    cudaGetSymbolAddress((void**)&pPaHi, g_pa_hi);
    cudaGetSymbolAddress((void**)&pPaLo, g_pa_lo);
    cudaGetSymbolAddress((void**)&pPrHi, g_pr_hi);
    cudaGetSymbolAddress((void**)&pPrLo, g_pr_lo);
    cudaGetSymbolAddress((void**)&pFcHi, g_fc_hi);
    cudaGetSymbolAddress((void**)&pFcLo, g_fc_lo);
    cudaGetSymbolAddress((void**)&pMxHi, g_mx_hi);
    cudaGetSymbolAddress((void**)&pMxLo, g_mx_lo);

    cudaFuncSetAttribute(hmma_gemm_kernel<0>, cudaFuncAttributeMaxDynamicSharedMemorySize, SM_TOTAL);
    cudaFuncSetAttribute(hmma_gemm_kernel<1>, cudaFuncAttributeMaxDynamicSharedMemorySize, SM_TOTAL);

    prep_kernel<<<PP, 256>>>(protos, lin_w);

    split_kernel<<<(BB * DD / 4) / 256, 256>>>(patient, pPaHi, pPaLo, BB * DD / 4);
    split_kernel<<<(PP * DD / 4) / 256, 256>>>(protos, pPrHi, pPrLo, PP * DD / 4);
    split_kernel<<<(PP * DD / 4) / 256, 256>>>(proto_fc_w, pFcHi, pFcLo, PP * DD / 4);

    // PW = protos @ W (fp32 SIMT)
    sgemm_nn_kernel<<<dim3(DD / 128, PP / 128), 256>>>(protos, bilinear_w, pPW, PP, DD, DD);

    // distance GEMM + per-tile top2
    hmma_gemm_kernel<0><<<dim3(PP / 128, BB / 128), 256, SM_TOTAL>>>(
        pPaHi, pPaLo, pPrHi, pPrLo, pPsq, (float*)pTop2);

    argmin_reduce_kernel<<<BB / 8, 256>>>(patient, protos);

    lam_kernel<<<BB / 8, 256>>>(index, bilinear_b, protos);

    mix_kernel<<<BB, 256>>>(patient, index);

    // logits GEMM (+bias, leaky)
    hmma_gemm_kernel<1><<<dim3(PP / 128, BB / 128), 256, SM_TOTAL>>>(
        pMxHi, pMxLo, pFcHi, pFcLo, proto_fc_b, pLogits);

    class_kernel<<<BB / 8, 256>>>(class_fc_w, class_fc_b, out);
}